// round 2
// baseline (speedup 1.0000x reference)
#include <cuda_runtime.h>
#include <cstdint>

// Problem constants
#define NB   8
#define CIN  16
#define LL   1024
#define DDIM 7
#define SZ   112     // CIN*DDIM
#define HH   16
#define DP   8       // padded head dim

// Scratch for Q/K/V in [n][h][l][8] layout (padded head dim), 4MB each.
__device__ float g_q[NB * HH * LL * DP];
__device__ float g_k[NB * HH * LL * DP];
__device__ float g_v[NB * HH * LL * DP];

// ---------------- f32x2 packed helpers (Blackwell FFMA2 path) ----------------
using u64 = unsigned long long;

__device__ __forceinline__ u64 pk2(float lo, float hi) {
    u64 r; asm("mov.b64 %0,{%1,%2};" : "=l"(r) : "f"(lo), "f"(hi)); return r;
}
__device__ __forceinline__ u64 dup2(float v) {
    u64 r; asm("mov.b64 %0,{%1,%1};" : "=l"(r) : "f"(v)); return r;
}
__device__ __forceinline__ void up2(u64 v, float& lo, float& hi) {
    asm("mov.b64 {%0,%1},%2;" : "=f"(lo), "=f"(hi) : "l"(v));
}
__device__ __forceinline__ u64 fma2(u64 a, u64 b, u64 c) {
    u64 d; asm("fma.rn.f32x2 %0,%1,%2,%3;" : "=l"(d) : "l"(a), "l"(b), "l"(c)); return d;
}
__device__ __forceinline__ u64 mul2(u64 a, u64 b) {
    u64 d; asm("mul.rn.f32x2 %0,%1,%2;" : "=l"(d) : "l"(a), "l"(b)); return d;
}
__device__ __forceinline__ u64 add2(u64 a, u64 b) {
    u64 d; asm("add.rn.f32x2 %0,%1,%2;" : "=l"(d) : "l"(a), "l"(b)); return d;
}
__device__ __forceinline__ float ex2f(float a) {
    float d; asm("ex2.approx.f32 %0,%1;" : "=f"(d) : "f"(a)); return d;
}

// ---------------- Kernel 1: fused transpose + QKV projection ----------------
// grid = (128, 3): blockIdx.x -> (n, l-tile of 64), blockIdx.y -> Wq/Wk/Wv.
// xs[64][116] tile of xf (transpose fused into load), ws[112][116] full W.
// 256 threads, each computes 4 rows x 7 cols as 2 f32x2 pairs x 7, with
// f-dimension vectorized float4 smem loads.
#define LDS_X 116
#define GEMM_SMEM ((64 * LDS_X + SZ * LDS_X) * 4)

__global__ void __launch_bounds__(256, 2)
qkv_gemm(const float* __restrict__ x,
         const float* __restrict__ Wq, const float* __restrict__ bq,
         const float* __restrict__ Wk, const float* __restrict__ bk,
         const float* __restrict__ Wv, const float* __restrict__ bv)
{
    extern __shared__ float sm[];
    float* xs = sm;                // [64][LDS_X]
    float* ws = sm + 64 * LDS_X;   // [112][LDS_X]

    const int tid = threadIdx.x;
    const int m = blockIdx.y;
    const float* W = (m == 0) ? Wq : ((m == 1) ? Wk : Wv);
    const float* b = (m == 0) ? bq : ((m == 1) ? bk : bv);
    float* og = (m == 0) ? g_q : ((m == 1) ? g_k : g_v);

    const int n  = blockIdx.x >> 4;          // 16 l-tiles per n
    const int l0 = (blockIdx.x & 15) << 6;

    // Load W [112][112] row-major into padded smem (coalesced)
    for (int i = tid; i < SZ * SZ; i += 256)
        ws[(i / SZ) * LDS_X + (i % SZ)] = W[i];

    // Load x tile, transposing [c][l][dd] -> xs[l][c*7+dd]; each c-chunk is
    // 448 contiguous floats in gmem -> coalesced.
    const float* xb = x + ((size_t)n * CIN * LL + l0) * DDIM;
    for (int i = tid; i < CIN * 64 * DDIM; i += 256) {
        int c = i / (64 * DDIM);
        int r = i - c * (64 * DDIM);
        float v = xb[(size_t)c * LL * DDIM + r];
        int l = r / DDIM;
        int dd = r - l * DDIM;
        xs[l * LDS_X + c * DDIM + dd] = v;
    }
    __syncthreads();

    const int tx = tid & 15;        // head / col group
    const int ty = tid >> 4;        // row group
    const int c0 = tx * 7;
    const int r0 = ty * 4;

    u64 acc[2][7];
#pragma unroll
    for (int j = 0; j < 7; ++j) {
        u64 bb = dup2(__ldg(&b[c0 + j]));
        acc[0][j] = bb; acc[1][j] = bb;
    }

#pragma unroll 4
    for (int f0 = 0; f0 < SZ; f0 += 4) {
        float4 x0 = *(const float4*)&xs[(r0 + 0) * LDS_X + f0];
        float4 x1 = *(const float4*)&xs[(r0 + 1) * LDS_X + f0];
        float4 x2 = *(const float4*)&xs[(r0 + 2) * LDS_X + f0];
        float4 x3 = *(const float4*)&xs[(r0 + 3) * LDS_X + f0];
        float4 wv[7];
#pragma unroll
        for (int j = 0; j < 7; ++j)
            wv[j] = *(const float4*)&ws[(c0 + j) * LDS_X + f0];

        const float xa0[4] = {x0.x, x0.y, x0.z, x0.w};
        const float xa1[4] = {x1.x, x1.y, x1.z, x1.w};
        const float xa2[4] = {x2.x, x2.y, x2.z, x2.w};
        const float xa3[4] = {x3.x, x3.y, x3.z, x3.w};
#pragma unroll
        for (int ff = 0; ff < 4; ++ff) {
            u64 p0 = pk2(xa0[ff], xa1[ff]);
            u64 p1 = pk2(xa2[ff], xa3[ff]);
            const float wa0[7] = {wv[0].x, wv[1].x, wv[2].x, wv[3].x, wv[4].x, wv[5].x, wv[6].x};
            const float wa1[7] = {wv[0].y, wv[1].y, wv[2].y, wv[3].y, wv[4].y, wv[5].y, wv[6].y};
            const float wa2[7] = {wv[0].z, wv[1].z, wv[2].z, wv[3].z, wv[4].z, wv[5].z, wv[6].z};
            const float wa3[7] = {wv[0].w, wv[1].w, wv[2].w, wv[3].w, wv[4].w, wv[5].w, wv[6].w};
            const float* wa = (ff == 0) ? wa0 : (ff == 1) ? wa1 : (ff == 2) ? wa2 : wa3;
#pragma unroll
            for (int j = 0; j < 7; ++j) {
                u64 wd = dup2(wa[j]);
                acc[0][j] = fma2(p0, wd, acc[0][j]);
                acc[1][j] = fma2(p1, wd, acc[1][j]);
            }
        }
    }

    // cols c0..c0+6 = head tx, dd = j. Store [n][h][l][8], pad dd=7 with 0.
    float* op = og + (((size_t)n * HH + tx) * LL + l0 + r0) * DP;
#pragma unroll
    for (int p = 0; p < 2; ++p) {
        float lo[7], hi[7];
#pragma unroll
        for (int j = 0; j < 7; ++j) up2(acc[p][j], lo[j], hi[j]);
        float* o0 = op + (2 * p) * DP;
        float* o1 = op + (2 * p + 1) * DP;
#pragma unroll
        for (int j = 0; j < 7; ++j) { o0[j] = lo[j]; o1[j] = hi[j]; }
        o0[7] = 0.0f; o1[7] = 0.0f;
    }
}

// ---------------- Kernel 2: fused softmax attention ----------------
// grid = 256 = (bh, query-half). block = 128 threads, each thread 4 query rows
// as 2 f32x2 pairs. K/V head tiles in smem (64KB -> 3 blocks/SM, single wave).
// exp via MUFU ex2.approx (scale log2e/32 pre-folded into q registers);
// softmax without max-subtraction (scores bounded after /32 scale).
#define ATT_SMEM (2 * LL * DP * 4)   // 64 KB

__global__ void __launch_bounds__(128, 3)
attn_kernel(float* __restrict__ out)
{
    extern __shared__ float sm[];
    float* ks = sm;            // [1024][8]
    float* vs = sm + LL * DP;  // [1024][8]

    const int tid  = threadIdx.x;
    const int bh   = blockIdx.x >> 1;     // n*16 + h
    const int half = blockIdx.x & 1;

    // Cooperative load of K and V head tiles (float4, coalesced)
    {
        const float4* k4 = (const float4*)(g_k + (size_t)bh * LL * DP);
        const float4* v4 = (const float4*)(g_v + (size_t)bh * LL * DP);
        float4* ks4 = (float4*)ks;
        float4* vs4 = (float4*)vs;
        for (int i = tid; i < LL * DP / 4; i += 128) {
            ks4[i] = k4[i];
            vs4[i] = v4[i];
        }
    }

    // This thread's 4 query rows; pre-scale by log2(e)/32 so score == ex2 arg.
    const int r0 = half * 512 + tid * 4;
    const float* qg = g_q + ((size_t)bh * LL + r0) * DP;
    const u64 SC = dup2(0.04508422002778011f);   // log2(e)/32
    u64 q0[7], q1[7];
    {
        float4 a0 = *(const float4*)(qg + 0);
        float4 a1 = *(const float4*)(qg + 4);
        float4 b0 = *(const float4*)(qg + 8);
        float4 b1 = *(const float4*)(qg + 12);
        float4 c0 = *(const float4*)(qg + 16);
        float4 c1 = *(const float4*)(qg + 20);
        float4 d0 = *(const float4*)(qg + 24);
        float4 d1 = *(const float4*)(qg + 28);
        q0[0] = mul2(pk2(a0.x, b0.x), SC); q0[1] = mul2(pk2(a0.y, b0.y), SC);
        q0[2] = mul2(pk2(a0.z, b0.z), SC); q0[3] = mul2(pk2(a0.w, b0.w), SC);
        q0[4] = mul2(pk2(a1.x, b1.x), SC); q0[5] = mul2(pk2(a1.y, b1.y), SC);
        q0[6] = mul2(pk2(a1.z, b1.z), SC);
        q1[0] = mul2(pk2(c0.x, d0.x), SC); q1[1] = mul2(pk2(c0.y, d0.y), SC);
        q1[2] = mul2(pk2(c0.z, d0.z), SC); q1[3] = mul2(pk2(c0.w, d0.w), SC);
        q1[4] = mul2(pk2(c1.x, d1.x), SC); q1[5] = mul2(pk2(c1.y, d1.y), SC);
        q1[6] = mul2(pk2(c1.z, d1.z), SC);
    }
    __syncthreads();

    u64 acc0[7], acc1[7];
    u64 S0 = dup2(0.0f), S1 = dup2(0.0f);
#pragma unroll
    for (int j = 0; j < 7; ++j) { acc0[j] = S0; acc1[j] = S0; }

#pragma unroll 2
    for (int key = 0; key < LL; ++key) {
        float4 ka = *(const float4*)&ks[key * DP];
        float4 kb = *(const float4*)&ks[key * DP + 4];
        u64 k0 = dup2(ka.x), k1 = dup2(ka.y), k2 = dup2(ka.z), k3 = dup2(ka.w);
        u64 k4 = dup2(kb.x), k5 = dup2(kb.y), k6 = dup2(kb.z);

        u64 s0 = mul2(q0[0], k0);
        u64 s1 = mul2(q1[0], k0);
        s0 = fma2(q0[1], k1, s0); s1 = fma2(q1[1], k1, s1);
        s0 = fma2(q0[2], k2, s0); s1 = fma2(q1[2], k2, s1);
        s0 = fma2(q0[3], k3, s0); s1 = fma2(q1[3], k3, s1);
        s0 = fma2(q0[4], k4, s0); s1 = fma2(q1[4], k4, s1);
        s0 = fma2(q0[5], k5, s0); s1 = fma2(q1[5], k5, s1);
        s0 = fma2(q0[6], k6, s0); s1 = fma2(q1[6], k6, s1);

        // exp2 via MUFU (scale already folded into q)
        float e0, e1, e2, e3;
        up2(s0, e0, e1);
        up2(s1, e2, e3);
        u64 p0 = pk2(ex2f(e0), ex2f(e1));
        u64 p1 = pk2(ex2f(e2), ex2f(e3));
        S0 = add2(S0, p0);
        S1 = add2(S1, p1);

        float4 va = *(const float4*)&vs[key * DP];
        float4 vb = *(const float4*)&vs[key * DP + 4];
        u64 v0 = dup2(va.x), v1 = dup2(va.y), v2 = dup2(va.z), v3 = dup2(va.w);
        u64 v4 = dup2(vb.x), v5 = dup2(vb.y), v6 = dup2(vb.z);

        acc0[0] = fma2(p0, v0, acc0[0]); acc1[0] = fma2(p1, v0, acc1[0]);
        acc0[1] = fma2(p0, v1, acc0[1]); acc1[1] = fma2(p1, v1, acc1[1]);
        acc0[2] = fma2(p0, v2, acc0[2]); acc1[2] = fma2(p1, v2, acc1[2]);
        acc0[3] = fma2(p0, v3, acc0[3]); acc1[3] = fma2(p1, v3, acc1[3]);
        acc0[4] = fma2(p0, v4, acc0[4]); acc1[4] = fma2(p1, v4, acc1[4]);
        acc0[5] = fma2(p0, v5, acc0[5]); acc1[5] = fma2(p1, v5, acc1[5]);
        acc0[6] = fma2(p0, v6, acc0[6]); acc1[6] = fma2(p1, v6, acc1[6]);
    }

    // Normalize and store (output layout [N,H,L,7])
    float sA, sB, sC, sD;
    up2(S0, sA, sB);
    up2(S1, sC, sD);
    float iA = 1.0f / sA, iB = 1.0f / sB, iC = 1.0f / sC, iD = 1.0f / sD;

    float* op = out + ((size_t)bh * LL + r0) * DDIM;
#pragma unroll
    for (int j = 0; j < 7; ++j) {
        float a, b, c, d;
        up2(acc0[j], a, b);
        up2(acc1[j], c, d);
        op[j]            = a * iA;
        op[DDIM + j]     = b * iB;
        op[2 * DDIM + j] = c * iC;
        op[3 * DDIM + j] = d * iD;
    }
}

// ---------------- launch ----------------
extern "C" void kernel_launch(void* const* d_in, const int* in_sizes, int n_in,
                              void* d_out, int out_size)
{
    const float* x  = (const float*)d_in[0];
    const float* Wq = (const float*)d_in[1];
    const float* bq = (const float*)d_in[2];
    const float* Wk = (const float*)d_in[3];
    const float* bk = (const float*)d_in[4];
    const float* Wv = (const float*)d_in[5];
    const float* bv = (const float*)d_in[6];

    cudaFuncSetAttribute(qkv_gemm, cudaFuncAttributeMaxDynamicSharedMemorySize, GEMM_SMEM);
    cudaFuncSetAttribute(attn_kernel, cudaFuncAttributeMaxDynamicSharedMemorySize, ATT_SMEM);

    qkv_gemm<<<dim3(128, 3), 256, GEMM_SMEM>>>(x, Wq, bq, Wk, bk, Wv, bv);
    attn_kernel<<<256, 128, ATT_SMEM>>>((float*)d_out);
}

// round 3
// speedup vs baseline: 1.9184x; 1.9184x over previous
#include <cuda_runtime.h>
#include <cstdint>

// Problem constants
#define NB   8
#define CIN  16
#define LL   1024
#define DDIM 7
#define SZ   112     // CIN*DDIM
#define HH   16
#define DP   8       // padded head dim
#define SPLIT 8
#define KCH  (LL / SPLIT)   // 128 keys per block

// Scratch: Q/K/V in [n][h][l][8] (4MB each), partials [ks][bh][l][8] (33.5MB)
__device__ float g_q[NB * HH * LL * DP];
__device__ float g_k[NB * HH * LL * DP];
__device__ float g_v[NB * HH * LL * DP];
__device__ float g_part[SPLIT * NB * HH * LL * DP];

// ---------------- f32x2 packed helpers ----------------
using u64 = unsigned long long;

__device__ __forceinline__ u64 pk2(float lo, float hi) {
    u64 r; asm("mov.b64 %0,{%1,%2};" : "=l"(r) : "f"(lo), "f"(hi)); return r;
}
__device__ __forceinline__ u64 dup2(float v) {
    u64 r; asm("mov.b64 %0,{%1,%1};" : "=l"(r) : "f"(v)); return r;
}
__device__ __forceinline__ void up2(u64 v, float& lo, float& hi) {
    asm("mov.b64 {%0,%1},%2;" : "=f"(lo), "=f"(hi) : "l"(v));
}
__device__ __forceinline__ u64 fma2(u64 a, u64 b, u64 c) {
    u64 d; asm("fma.rn.f32x2 %0,%1,%2,%3;" : "=l"(d) : "l"(a), "l"(b), "l"(c)); return d;
}
__device__ __forceinline__ u64 mul2(u64 a, u64 b) {
    u64 d; asm("mul.rn.f32x2 %0,%1,%2;" : "=l"(d) : "l"(a), "l"(b)); return d;
}
__device__ __forceinline__ u64 add2(u64 a, u64 b) {
    u64 d; asm("add.rn.f32x2 %0,%1,%2;" : "=l"(d) : "l"(a), "l"(b)); return d;
}
__device__ __forceinline__ float ex2f(float a) {
    float d; asm("ex2.approx.f32 %0,%1;" : "=f"(d) : "f"(a)); return d;
}

// ---------------- Kernel 1: fused transpose + QKV projection ----------------
// grid (64, 3): bx -> (n, l-tile of 128), by -> Wq/Wk/Wv.
// xs_t[f][l] transposed tile (stride 132) so query-row pairs load as LDS.128.
// 256 threads: each 8 rows x 7 cols as 4 f32x2 pairs x 7 accumulators.
#define SXT 132
#define SWS 113
#define GEMM_SMEM ((SZ * SXT + SZ * SWS) * 4)

__global__ void __launch_bounds__(256)
qkv_gemm(const float* __restrict__ x,
         const float* __restrict__ Wq, const float* __restrict__ bq,
         const float* __restrict__ Wk, const float* __restrict__ bk,
         const float* __restrict__ Wv, const float* __restrict__ bv)
{
    extern __shared__ float sm[];
    float* xs = sm;             // [112 f][SXT] transposed x tile
    float* ws = sm + SZ * SXT;  // [112 c][SWS]

    const int tid = threadIdx.x;
    const int m = blockIdx.y;
    const float* W = (m == 0) ? Wq : ((m == 1) ? Wk : Wv);
    const float* b = (m == 0) ? bq : ((m == 1) ? bk : bv);
    float* og = (m == 0) ? g_q : ((m == 1) ? g_k : g_v);

    const int n  = blockIdx.x >> 3;
    const int l0 = (blockIdx.x & 7) << 7;

    for (int i = tid; i < SZ * SZ; i += 256)
        ws[(i / SZ) * SWS + (i % SZ)] = W[i];

    // x [c][l][dd] -> xs[f=c*7+dd][l] (coalesced gmem reads)
    const float* xb = x + ((size_t)n * CIN * LL + l0) * DDIM;
    for (int i = tid; i < CIN * 128 * DDIM; i += 256) {
        int c = i / (128 * DDIM);
        int r = i - c * (128 * DDIM);
        float v = xb[(size_t)c * LL * DDIM + r];
        int l = r / DDIM;
        int dd = r - l * DDIM;
        xs[(c * DDIM + dd) * SXT + l] = v;
    }
    __syncthreads();

    const int tx = tid & 15;    // head / col group
    const int ty = tid >> 4;    // row group
    const int c0 = tx * 7;
    const int r0 = ty * 8;

    u64 acc[4][7];
#pragma unroll
    for (int j = 0; j < 7; ++j) {
        u64 bb = dup2(__ldg(&b[c0 + j]));
        acc[0][j] = bb; acc[1][j] = bb; acc[2][j] = bb; acc[3][j] = bb;
    }

#pragma unroll 2
    for (int f = 0; f < SZ; ++f) {
        float4 xa = *(const float4*)&xs[f * SXT + r0];
        float4 xb4 = *(const float4*)&xs[f * SXT + r0 + 4];
        u64 xp0 = pk2(xa.x, xa.y), xp1 = pk2(xa.z, xa.w);
        u64 xp2 = pk2(xb4.x, xb4.y), xp3 = pk2(xb4.z, xb4.w);
        const float* wr = &ws[c0 * SWS + f];
#pragma unroll
        for (int j = 0; j < 7; ++j) {
            u64 wd = dup2(wr[j * SWS]);
            acc[0][j] = fma2(xp0, wd, acc[0][j]);
            acc[1][j] = fma2(xp1, wd, acc[1][j]);
            acc[2][j] = fma2(xp2, wd, acc[2][j]);
            acc[3][j] = fma2(xp3, wd, acc[3][j]);
        }
    }

    // cols c0..c0+6 = head tx, dd = j. Store [n][h][l][8], pad with 0.
    float* op = og + (((size_t)n * HH + tx) * LL + l0 + r0) * DP;
#pragma unroll
    for (int p = 0; p < 4; ++p) {
        float lo[7], hi[7];
#pragma unroll
        for (int j = 0; j < 7; ++j) up2(acc[p][j], lo[j], hi[j]);
        float4* o0 = (float4*)(op + (2 * p) * DP);
        float4* o1 = (float4*)(op + (2 * p + 1) * DP);
        o0[0] = make_float4(lo[0], lo[1], lo[2], lo[3]);
        o0[1] = make_float4(lo[4], lo[5], lo[6], 0.0f);
        o1[0] = make_float4(hi[0], hi[1], hi[2], hi[3]);
        o1[1] = make_float4(hi[4], hi[5], hi[6], 0.0f);
    }
}

// ---------------- Kernel 2: key-split attention partials ----------------
// grid 1024 = (bh, key-chunk of 128). 256 threads, each 4 query rows as
// 2 f32x2 pairs over ALL queries. K/V stored PRE-DUPLICATED as f32x2 in smem
// (14KB) so inner loop is broadcast LDS.64 straight into FFMA2 operands.
// No max-subtraction softmax => partials are exact sums, split-safe.
__global__ void __launch_bounds__(256, 2)
attn_kernel()
{
    __shared__ u64 kd[KCH * 7];
    __shared__ u64 vd[KCH * 7];

    const int tid = threadIdx.x;
    const int bh  = blockIdx.x >> 3;
    const int ks  = blockIdx.x & 7;
    const int kbase = ks * KCH;

    // Build duplicated K/V chunk (coalesced float4 reads)
    if (tid < KCH) {
        const float4* kp = (const float4*)(g_k + ((size_t)bh * LL + kbase + tid) * DP);
        float4 a = kp[0], c = kp[1];
        u64* o = kd + tid * 7;
        o[0] = dup2(a.x); o[1] = dup2(a.y); o[2] = dup2(a.z); o[3] = dup2(a.w);
        o[4] = dup2(c.x); o[5] = dup2(c.y); o[6] = dup2(c.z);
    } else {
        int t = tid - KCH;
        const float4* vp = (const float4*)(g_v + ((size_t)bh * LL + kbase + t) * DP);
        float4 a = vp[0], c = vp[1];
        u64* o = vd + t * 7;
        o[0] = dup2(a.x); o[1] = dup2(a.y); o[2] = dup2(a.z); o[3] = dup2(a.w);
        o[4] = dup2(c.x); o[5] = dup2(c.y); o[6] = dup2(c.z);
    }

    // This thread's 4 query rows; fold log2(e)/32 into q.
    const int r0 = tid * 4;
    const float* qg = g_q + ((size_t)bh * LL + r0) * DP;
    const u64 SC = dup2(0.04508422002778011f);   // log2(e)/32
    u64 q0[7], q1[7];
    {
        float4 a0 = *(const float4*)(qg + 0);
        float4 a1 = *(const float4*)(qg + 4);
        float4 b0 = *(const float4*)(qg + 8);
        float4 b1 = *(const float4*)(qg + 12);
        float4 c0 = *(const float4*)(qg + 16);
        float4 c1 = *(const float4*)(qg + 20);
        float4 d0 = *(const float4*)(qg + 24);
        float4 d1 = *(const float4*)(qg + 28);
        q0[0] = mul2(pk2(a0.x, b0.x), SC); q0[1] = mul2(pk2(a0.y, b0.y), SC);
        q0[2] = mul2(pk2(a0.z, b0.z), SC); q0[3] = mul2(pk2(a0.w, b0.w), SC);
        q0[4] = mul2(pk2(a1.x, b1.x), SC); q0[5] = mul2(pk2(a1.y, b1.y), SC);
        q0[6] = mul2(pk2(a1.z, b1.z), SC);
        q1[0] = mul2(pk2(c0.x, d0.x), SC); q1[1] = mul2(pk2(c0.y, d0.y), SC);
        q1[2] = mul2(pk2(c0.z, d0.z), SC); q1[3] = mul2(pk2(c0.w, d0.w), SC);
        q1[4] = mul2(pk2(c1.x, d1.x), SC); q1[5] = mul2(pk2(c1.y, d1.y), SC);
        q1[6] = mul2(pk2(c1.z, d1.z), SC);
    }
    __syncthreads();

    u64 acc0[7], acc1[7];
    u64 S0 = dup2(0.0f), S1 = dup2(0.0f);
#pragma unroll
    for (int j = 0; j < 7; ++j) { acc0[j] = S0; acc1[j] = S0; }

#pragma unroll 2
    for (int key = 0; key < KCH; ++key) {
        const u64* kk = kd + key * 7;
        u64 s0 = mul2(q0[0], kk[0]);
        u64 s1 = mul2(q1[0], kk[0]);
        s0 = fma2(q0[1], kk[1], s0); s1 = fma2(q1[1], kk[1], s1);
        s0 = fma2(q0[2], kk[2], s0); s1 = fma2(q1[2], kk[2], s1);
        s0 = fma2(q0[3], kk[3], s0); s1 = fma2(q1[3], kk[3], s1);
        s0 = fma2(q0[4], kk[4], s0); s1 = fma2(q1[4], kk[4], s1);
        s0 = fma2(q0[5], kk[5], s0); s1 = fma2(q1[5], kk[5], s1);
        s0 = fma2(q0[6], kk[6], s0); s1 = fma2(q1[6], kk[6], s1);

        float e0, e1, e2, e3;
        up2(s0, e0, e1);
        up2(s1, e2, e3);
        u64 p0 = pk2(ex2f(e0), ex2f(e1));
        u64 p1 = pk2(ex2f(e2), ex2f(e3));
        S0 = add2(S0, p0);
        S1 = add2(S1, p1);

        const u64* vv = vd + key * 7;
        acc0[0] = fma2(p0, vv[0], acc0[0]); acc1[0] = fma2(p1, vv[0], acc1[0]);
        acc0[1] = fma2(p0, vv[1], acc0[1]); acc1[1] = fma2(p1, vv[1], acc1[1]);
        acc0[2] = fma2(p0, vv[2], acc0[2]); acc1[2] = fma2(p1, vv[2], acc1[2]);
        acc0[3] = fma2(p0, vv[3], acc0[3]); acc1[3] = fma2(p1, vv[3], acc1[3]);
        acc0[4] = fma2(p0, vv[4], acc0[4]); acc1[4] = fma2(p1, vv[4], acc1[4]);
        acc0[5] = fma2(p0, vv[5], acc0[5]); acc1[5] = fma2(p1, vv[5], acc1[5]);
        acc0[6] = fma2(p0, vv[6], acc0[6]); acc1[6] = fma2(p1, vv[6], acc1[6]);
    }

    // Write partials: [ks][bh][l][8] = {acc0..6, S}
    float* pp = g_part + (((size_t)(ks * NB * HH + bh)) * LL + r0) * DP;
    float lo[7], hi[7], sl, sh;
#pragma unroll
    for (int j = 0; j < 7; ++j) up2(acc0[j], lo[j], hi[j]);
    up2(S0, sl, sh);
    ((float4*)pp)[0] = make_float4(lo[0], lo[1], lo[2], lo[3]);
    ((float4*)pp)[1] = make_float4(lo[4], lo[5], lo[6], sl);
    ((float4*)pp)[2] = make_float4(hi[0], hi[1], hi[2], hi[3]);
    ((float4*)pp)[3] = make_float4(hi[4], hi[5], hi[6], sh);
#pragma unroll
    for (int j = 0; j < 7; ++j) up2(acc1[j], lo[j], hi[j]);
    up2(S1, sl, sh);
    ((float4*)pp)[4] = make_float4(lo[0], lo[1], lo[2], lo[3]);
    ((float4*)pp)[5] = make_float4(lo[4], lo[5], lo[6], sl);
    ((float4*)pp)[6] = make_float4(hi[0], hi[1], hi[2], hi[3]);
    ((float4*)pp)[7] = make_float4(hi[4], hi[5], hi[6], sh);
}

// ---------------- Kernel 3: combine partials + normalize ----------------
__global__ void __launch_bounds__(256)
reduce_kernel(float* __restrict__ out)
{
    const int qi = blockIdx.x * 256 + threadIdx.x;   // 131072 queries
    const int bh = qi >> 10;
    const int l  = qi & 1023;

    float a0 = 0, a1 = 0, a2 = 0, a3 = 0, a4 = 0, a5 = 0, a6 = 0, S = 0;
#pragma unroll
    for (int ks = 0; ks < SPLIT; ++ks) {
        const float4* p = (const float4*)(g_part +
            (((size_t)(ks * NB * HH + bh)) * LL + l) * DP);
        float4 a = p[0], b = p[1];
        a0 += a.x; a1 += a.y; a2 += a.z; a3 += a.w;
        a4 += b.x; a5 += b.y; a6 += b.z; S  += b.w;
    }
    float inv = 1.0f / S;
    float* op = out + (size_t)qi * DDIM;
    op[0] = a0 * inv; op[1] = a1 * inv; op[2] = a2 * inv;
    op[3] = a3 * inv; op[4] = a4 * inv; op[5] = a5 * inv;
    op[6] = a6 * inv;
}

// ---------------- launch ----------------
extern "C" void kernel_launch(void* const* d_in, const int* in_sizes, int n_in,
                              void* d_out, int out_size)
{
    const float* x  = (const float*)d_in[0];
    const float* Wq = (const float*)d_in[1];
    const float* bq = (const float*)d_in[2];
    const float* Wk = (const float*)d_in[3];
    const float* bk = (const float*)d_in[4];
    const float* Wv = (const float*)d_in[5];
    const float* bv = (const float*)d_in[6];

    cudaFuncSetAttribute(qkv_gemm, cudaFuncAttributeMaxDynamicSharedMemorySize, GEMM_SMEM);
    cudaFuncSetAttribute(qkv_gemm, cudaFuncAttributePreferredSharedMemoryCarveout, 100);
    cudaFuncSetAttribute(attn_kernel, cudaFuncAttributePreferredSharedMemoryCarveout, 100);

    qkv_gemm<<<dim3(64, 3), 256, GEMM_SMEM>>>(x, Wq, bq, Wk, bk, Wv, bv);
    attn_kernel<<<NB * HH * SPLIT, 256>>>();
    reduce_kernel<<<NB * HH * LL / 256, 256>>>((float*)d_out);
}

// round 4
// speedup vs baseline: 1.9892x; 1.0369x over previous
#include <cuda_runtime.h>
#include <cstdint>

// Problem constants
#define NB   8
#define CIN  16
#define LL   1024
#define DDIM 7
#define SZ   112     // CIN*DDIM
#define HH   16
#define DP   8       // padded head dim
#define SPLIT 8
#define KCH  (LL / SPLIT)   // 128 keys per block

// Scratch: Q/K/V in [n][h][l][8] (4MB each), partials [ks][bh][l][8]
__device__ float g_q[NB * HH * LL * DP];   // NOTE: q pre-scaled by log2(e)/32
__device__ float g_k[NB * HH * LL * DP];
__device__ float g_v[NB * HH * LL * DP];
__device__ float g_part[SPLIT * NB * HH * LL * DP];

// ---------------- f32x2 packed helpers ----------------
using u64 = unsigned long long;

__device__ __forceinline__ u64 pk2(float lo, float hi) {
    u64 r; asm("mov.b64 %0,{%1,%2};" : "=l"(r) : "f"(lo), "f"(hi)); return r;
}
__device__ __forceinline__ u64 dup2(float v) {
    u64 r; asm("mov.b64 %0,{%1,%1};" : "=l"(r) : "f"(v)); return r;
}
__device__ __forceinline__ void up2(u64 v, float& lo, float& hi) {
    asm("mov.b64 {%0,%1},%2;" : "=f"(lo), "=f"(hi) : "l"(v));
}
__device__ __forceinline__ u64 fma2(u64 a, u64 b, u64 c) {
    u64 d; asm("fma.rn.f32x2 %0,%1,%2,%3;" : "=l"(d) : "l"(a), "l"(b), "l"(c)); return d;
}
__device__ __forceinline__ u64 mul2(u64 a, u64 b) {
    u64 d; asm("mul.rn.f32x2 %0,%1,%2;" : "=l"(d) : "l"(a), "l"(b)); return d;
}
__device__ __forceinline__ u64 add2(u64 a, u64 b) {
    u64 d; asm("add.rn.f32x2 %0,%1,%2;" : "=l"(d) : "l"(a), "l"(b)); return d;
}
__device__ __forceinline__ float ex2f(float a) {
    float d; asm("ex2.approx.f32 %0,%1;" : "=f"(d) : "f"(a)); return d;
}

// ---------------- Kernel 1: fused transpose + QKV projection ----------------
// grid (64, 3), 512 threads: bx -> (n, l-tile of 128), by -> Wq/Wk/Wv.
// xs_t[f][l] (stride 132), ws[c][f] (stride 116, float4 over f).
// Each thread: 4 rows (2 f32x2 pairs) x 7 cols; 16 warps/block for latency hiding.
#define SXT 132
#define SWS 116
#define GEMM_SMEM ((SZ * SXT + SZ * SWS) * 4)

__global__ void __launch_bounds__(512, 1)
qkv_gemm(const float* __restrict__ x,
         const float* __restrict__ Wq, const float* __restrict__ bq,
         const float* __restrict__ Wk, const float* __restrict__ bk,
         const float* __restrict__ Wv, const float* __restrict__ bv)
{
    extern __shared__ float sm[];
    float* xs = sm;             // [112 f][SXT]
    float* ws = sm + SZ * SXT;  // [112 c][SWS]

    const int tid = threadIdx.x;
    const int m = blockIdx.y;
    const float* W = (m == 0) ? Wq : ((m == 1) ? Wk : Wv);
    const float* b = (m == 0) ? bq : ((m == 1) ? bk : bv);
    float* og = (m == 0) ? g_q : ((m == 1) ? g_k : g_v);

    const int n  = blockIdx.x >> 3;
    const int l0 = (blockIdx.x & 7) << 7;

    for (int i = tid; i < SZ * SZ; i += 512)
        ws[(i / SZ) * SWS + (i % SZ)] = W[i];

    // x [c][l][dd] -> xs[f=c*7+dd][l]
    const float* xb = x + ((size_t)n * CIN * LL + l0) * DDIM;
    for (int i = tid; i < CIN * 128 * DDIM; i += 512) {
        int c = i / (128 * DDIM);
        int r = i - c * (128 * DDIM);
        float v = xb[(size_t)c * LL * DDIM + r];
        int l = r / DDIM;
        int dd = r - l * DDIM;
        xs[(c * DDIM + dd) * SXT + l] = v;
    }
    __syncthreads();

    const int tx = tid & 15;    // head / col group
    const int ty = tid >> 4;    // row group (0..31)
    const int c0 = tx * 7;
    const int r0 = ty * 4;

    u64 acc[2][7];
#pragma unroll
    for (int j = 0; j < 7; ++j) {
        u64 bb = dup2(__ldg(&b[c0 + j]));
        acc[0][j] = bb; acc[1][j] = bb;
    }

#pragma unroll 2
    for (int f0 = 0; f0 < SZ; f0 += 4) {
        float4 xa[4];
#pragma unroll
        for (int ff = 0; ff < 4; ++ff)
            xa[ff] = *(const float4*)&xs[(f0 + ff) * SXT + r0];
        float4 w4[7];
#pragma unroll
        for (int j = 0; j < 7; ++j)
            w4[j] = *(const float4*)&ws[(c0 + j) * SWS + f0];

#pragma unroll
        for (int ff = 0; ff < 4; ++ff) {
            u64 xp0 = pk2(xa[ff].x, xa[ff].y);
            u64 xp1 = pk2(xa[ff].z, xa[ff].w);
            const float wv[7] = {
                (ff == 0) ? w4[0].x : (ff == 1) ? w4[0].y : (ff == 2) ? w4[0].z : w4[0].w,
                (ff == 0) ? w4[1].x : (ff == 1) ? w4[1].y : (ff == 2) ? w4[1].z : w4[1].w,
                (ff == 0) ? w4[2].x : (ff == 1) ? w4[2].y : (ff == 2) ? w4[2].z : w4[2].w,
                (ff == 0) ? w4[3].x : (ff == 1) ? w4[3].y : (ff == 2) ? w4[3].z : w4[3].w,
                (ff == 0) ? w4[4].x : (ff == 1) ? w4[4].y : (ff == 2) ? w4[4].z : w4[4].w,
                (ff == 0) ? w4[5].x : (ff == 1) ? w4[5].y : (ff == 2) ? w4[5].z : w4[5].w,
                (ff == 0) ? w4[6].x : (ff == 1) ? w4[6].y : (ff == 2) ? w4[6].z : w4[6].w };
#pragma unroll
            for (int j = 0; j < 7; ++j) {
                u64 wd = dup2(wv[j]);
                acc[0][j] = fma2(xp0, wd, acc[0][j]);
                acc[1][j] = fma2(xp1, wd, acc[1][j]);
            }
        }
    }

    // For Q, fold in log2(e)/32 so attention needs no per-key scale.
    if (m == 0) {
        const u64 SC = dup2(0.04508422002778011f);
#pragma unroll
        for (int j = 0; j < 7; ++j) {
            acc[0][j] = mul2(acc[0][j], SC);
            acc[1][j] = mul2(acc[1][j], SC);
        }
    }

    // cols c0..c0+6 = head tx, dd = j. Store [n][h][l][8], pad with 0.
    float* op = og + (((size_t)n * HH + tx) * LL + l0 + r0) * DP;
#pragma unroll
    for (int p = 0; p < 2; ++p) {
        float lo[7], hi[7];
#pragma unroll
        for (int j = 0; j < 7; ++j) up2(acc[p][j], lo[j], hi[j]);
        float4* o0 = (float4*)(op + (2 * p) * DP);
        float4* o1 = (float4*)(op + (2 * p + 1) * DP);
        o0[0] = make_float4(lo[0], lo[1], lo[2], lo[3]);
        o0[1] = make_float4(lo[4], lo[5], lo[6], 0.0f);
        o1[0] = make_float4(hi[0], hi[1], hi[2], hi[3]);
        o1[1] = make_float4(hi[4], hi[5], hi[6], 0.0f);
    }
}

// ---------------- Kernel 2: key-split attention partials ----------------
// grid 1024 = (bh, key-chunk of 128). 256 threads, each 4 query rows as
// 2 f32x2 pairs. K/V pre-duplicated as f32x2 in smem, 8 u64/key stride so
// the inner loop reads them as LDS.128 pairs. Split-safe exact-sum softmax.
__global__ void __launch_bounds__(256, 2)
attn_kernel()
{
    __shared__ u64 kd[KCH * 8];
    __shared__ u64 vd[KCH * 8];

    const int tid = threadIdx.x;
    const int bh  = blockIdx.x >> 3;
    const int ks  = blockIdx.x & 7;
    const int kbase = ks * KCH;

    // Build duplicated K/V chunk (coalesced float4 reads, stride-8 u64 rows)
    if (tid < KCH) {
        const float4* kp = (const float4*)(g_k + ((size_t)bh * LL + kbase + tid) * DP);
        float4 a = kp[0], c = kp[1];
        u64* o = kd + tid * 8;
        o[0] = dup2(a.x); o[1] = dup2(a.y); o[2] = dup2(a.z); o[3] = dup2(a.w);
        o[4] = dup2(c.x); o[5] = dup2(c.y); o[6] = dup2(c.z); o[7] = 0ull;
    } else {
        int t = tid - KCH;
        const float4* vp = (const float4*)(g_v + ((size_t)bh * LL + kbase + t) * DP);
        float4 a = vp[0], c = vp[1];
        u64* o = vd + t * 8;
        o[0] = dup2(a.x); o[1] = dup2(a.y); o[2] = dup2(a.z); o[3] = dup2(a.w);
        o[4] = dup2(c.x); o[5] = dup2(c.y); o[6] = dup2(c.z); o[7] = 0ull;
    }

    // This thread's 4 query rows (q already scaled by log2(e)/32 in gemm).
    const int r0 = tid * 4;
    const float* qg = g_q + ((size_t)bh * LL + r0) * DP;
    u64 q0[7], q1[7];
    {
        float4 a0 = *(const float4*)(qg + 0);
        float4 a1 = *(const float4*)(qg + 4);
        float4 b0 = *(const float4*)(qg + 8);
        float4 b1 = *(const float4*)(qg + 12);
        float4 c0 = *(const float4*)(qg + 16);
        float4 c1 = *(const float4*)(qg + 20);
        float4 d0 = *(const float4*)(qg + 24);
        float4 d1 = *(const float4*)(qg + 28);
        q0[0] = pk2(a0.x, b0.x); q0[1] = pk2(a0.y, b0.y); q0[2] = pk2(a0.z, b0.z);
        q0[3] = pk2(a0.w, b0.w); q0[4] = pk2(a1.x, b1.x); q0[5] = pk2(a1.y, b1.y);
        q0[6] = pk2(a1.z, b1.z);
        q1[0] = pk2(c0.x, d0.x); q1[1] = pk2(c0.y, d0.y); q1[2] = pk2(c0.z, d0.z);
        q1[3] = pk2(c0.w, d0.w); q1[4] = pk2(c1.x, d1.x); q1[5] = pk2(c1.y, d1.y);
        q1[6] = pk2(c1.z, d1.z);
    }
    __syncthreads();

    u64 acc0[7], acc1[7];
    u64 S0 = dup2(0.0f), S1 = dup2(0.0f);
#pragma unroll
    for (int j = 0; j < 7; ++j) { acc0[j] = S0; acc1[j] = S0; }

#pragma unroll 4
    for (int key = 0; key < KCH; ++key) {
        ulonglong2 ka = *(const ulonglong2*)(kd + key * 8);
        ulonglong2 kb = *(const ulonglong2*)(kd + key * 8 + 2);
        ulonglong2 kc = *(const ulonglong2*)(kd + key * 8 + 4);
        ulonglong2 ke = *(const ulonglong2*)(kd + key * 8 + 6);

        u64 s0 = mul2(q0[0], ka.x);
        u64 s1 = mul2(q1[0], ka.x);
        s0 = fma2(q0[1], ka.y, s0); s1 = fma2(q1[1], ka.y, s1);
        s0 = fma2(q0[2], kb.x, s0); s1 = fma2(q1[2], kb.x, s1);
        s0 = fma2(q0[3], kb.y, s0); s1 = fma2(q1[3], kb.y, s1);
        s0 = fma2(q0[4], kc.x, s0); s1 = fma2(q1[4], kc.x, s1);
        s0 = fma2(q0[5], kc.y, s0); s1 = fma2(q1[5], kc.y, s1);
        s0 = fma2(q0[6], ke.x, s0); s1 = fma2(q1[6], ke.x, s1);

        float e0, e1, e2, e3;
        up2(s0, e0, e1);
        up2(s1, e2, e3);
        u64 p0 = pk2(ex2f(e0), ex2f(e1));
        u64 p1 = pk2(ex2f(e2), ex2f(e3));
        S0 = add2(S0, p0);
        S1 = add2(S1, p1);

        ulonglong2 va = *(const ulonglong2*)(vd + key * 8);
        ulonglong2 vb = *(const ulonglong2*)(vd + key * 8 + 2);
        ulonglong2 vc = *(const ulonglong2*)(vd + key * 8 + 4);
        ulonglong2 ve = *(const ulonglong2*)(vd + key * 8 + 6);

        acc0[0] = fma2(p0, va.x, acc0[0]); acc1[0] = fma2(p1, va.x, acc1[0]);
        acc0[1] = fma2(p0, va.y, acc0[1]); acc1[1] = fma2(p1, va.y, acc1[1]);
        acc0[2] = fma2(p0, vb.x, acc0[2]); acc1[2] = fma2(p1, vb.x, acc1[2]);
        acc0[3] = fma2(p0, vb.y, acc0[3]); acc1[3] = fma2(p1, vb.y, acc1[3]);
        acc0[4] = fma2(p0, vc.x, acc0[4]); acc1[4] = fma2(p1, vc.x, acc1[4]);
        acc0[5] = fma2(p0, vc.y, acc0[5]); acc1[5] = fma2(p1, vc.y, acc1[5]);
        acc0[6] = fma2(p0, ve.x, acc0[6]); acc1[6] = fma2(p1, ve.x, acc1[6]);
    }

    // Write partials: [ks][bh][l][8] = {acc0..6, S}
    float* pp = g_part + (((size_t)(ks * NB * HH + bh)) * LL + r0) * DP;
    float lo[7], hi[7], sl, sh;
#pragma unroll
    for (int j = 0; j < 7; ++j) up2(acc0[j], lo[j], hi[j]);
    up2(S0, sl, sh);
    ((float4*)pp)[0] = make_float4(lo[0], lo[1], lo[2], lo[3]);
    ((float4*)pp)[1] = make_float4(lo[4], lo[5], lo[6], sl);
    ((float4*)pp)[2] = make_float4(hi[0], hi[1], hi[2], hi[3]);
    ((float4*)pp)[3] = make_float4(hi[4], hi[5], hi[6], sh);
#pragma unroll
    for (int j = 0; j < 7; ++j) up2(acc1[j], lo[j], hi[j]);
    up2(S1, sl, sh);
    ((float4*)pp)[4] = make_float4(lo[0], lo[1], lo[2], lo[3]);
    ((float4*)pp)[5] = make_float4(lo[4], lo[5], lo[6], sl);
    ((float4*)pp)[6] = make_float4(hi[0], hi[1], hi[2], hi[3]);
    ((float4*)pp)[7] = make_float4(hi[4], hi[5], hi[6], sh);
}

// ---------------- Kernel 3: combine partials + normalize ----------------
__global__ void __launch_bounds__(256)
reduce_kernel(float* __restrict__ out)
{
    const int qi = blockIdx.x * 256 + threadIdx.x;   // 131072 queries
    const int bh = qi >> 10;
    const int l  = qi & 1023;

    float a0 = 0, a1 = 0, a2 = 0, a3 = 0, a4 = 0, a5 = 0, a6 = 0, S = 0;
#pragma unroll
    for (int ks = 0; ks < SPLIT; ++ks) {
        const float4* p = (const float4*)(g_part +
            (((size_t)(ks * NB * HH + bh)) * LL + l) * DP);
        float4 a = p[0], b = p[1];
        a0 += a.x; a1 += a.y; a2 += a.z; a3 += a.w;
        a4 += b.x; a5 += b.y; a6 += b.z; S  += b.w;
    }
    float inv = 1.0f / S;
    float* op = out + (size_t)qi * DDIM;
    op[0] = a0 * inv; op[1] = a1 * inv; op[2] = a2 * inv;
    op[3] = a3 * inv; op[4] = a4 * inv; op[5] = a5 * inv;
    op[6] = a6 * inv;
}

// ---------------- launch ----------------
extern "C" void kernel_launch(void* const* d_in, const int* in_sizes, int n_in,
                              void* d_out, int out_size)
{
    const float* x  = (const float*)d_in[0];
    const float* Wq = (const float*)d_in[1];
    const float* bq = (const float*)d_in[2];
    const float* Wk = (const float*)d_in[3];
    const float* bk = (const float*)d_in[4];
    const float* Wv = (const float*)d_in[5];
    const float* bv = (const float*)d_in[6];

    cudaFuncSetAttribute(qkv_gemm, cudaFuncAttributeMaxDynamicSharedMemorySize, GEMM_SMEM);
    cudaFuncSetAttribute(qkv_gemm, cudaFuncAttributePreferredSharedMemoryCarveout, 100);
    cudaFuncSetAttribute(attn_kernel, cudaFuncAttributePreferredSharedMemoryCarveout, 100);

    qkv_gemm<<<dim3(64, 3), 512, GEMM_SMEM>>>(x, Wq, bq, Wk, bk, Wv, bv);
    attn_kernel<<<NB * HH * SPLIT, 256>>>();
    reduce_kernel<<<NB * HH * LL / 256, 256>>>((float*)d_out);
}